// round 4
// baseline (speedup 1.0000x reference)
#include <cuda_runtime.h>
#include <cuda_bf16.h>

#define D_MODEL 1024
#define SEQ     2048
#define BATCH   2
#define NHEAD   16
#define DHEAD   64
#define HB      32
#define MROWS   4096

typedef unsigned int u32;
typedef unsigned short u16;

// ---- device-global scratch (allocation-free) ----
__device__ u16 g_qh[(size_t)HB * SEQ * DHEAD];
__device__ u16 g_ql[(size_t)HB * SEQ * DHEAD];
__device__ u16 g_kh[(size_t)HB * SEQ * DHEAD];
__device__ u16 g_kl[(size_t)HB * SEQ * DHEAD];
__device__ u16 g_vh[(size_t)HB * SEQ * DHEAD];
__device__ u16 g_vl[(size_t)HB * SEQ * DHEAD];
__device__ float g_attn_fb[(size_t)HB * SEQ * SEQ];   // fallback sinks
__device__ float g_ctx_fb[(size_t)MROWS * D_MODEL];

// ---- PTX primitives ----
__device__ __forceinline__ void ldm_x4(u32 r[4], u32 addr) {
    asm volatile("ldmatrix.sync.aligned.m8n8.x4.shared.b16 {%0,%1,%2,%3}, [%4];"
                 : "=r"(r[0]), "=r"(r[1]), "=r"(r[2]), "=r"(r[3]) : "r"(addr));
}
__device__ __forceinline__ void ldm_x2(u32 r[2], u32 addr) {
    asm volatile("ldmatrix.sync.aligned.m8n8.x2.shared.b16 {%0,%1}, [%2];"
                 : "=r"(r[0]), "=r"(r[1]) : "r"(addr));
}
__device__ __forceinline__ void ldm_x2t(u32 r[2], u32 addr) {
    asm volatile("ldmatrix.sync.aligned.m8n8.x2.trans.shared.b16 {%0,%1}, [%2];"
                 : "=r"(r[0]), "=r"(r[1]) : "r"(addr));
}
__device__ __forceinline__ void mma16816(float d[4], const u32 a[4], const u32 b[2]) {
    asm volatile("mma.sync.aligned.m16n8k16.row.col.f32.bf16.bf16.f32 "
                 "{%0,%1,%2,%3}, {%4,%5,%6,%7}, {%8,%9}, {%0,%1,%2,%3};"
                 : "+f"(d[0]), "+f"(d[1]), "+f"(d[2]), "+f"(d[3])
                 : "r"(a[0]), "r"(a[1]), "r"(a[2]), "r"(a[3]), "r"(b[0]), "r"(b[1]));
}
__device__ __forceinline__ u32 smem_u32(const void* p) {
    return (u32)__cvta_generic_to_shared(p);
}
// split (x,y) into bf16 hi pair (ret) + lo pair (out param)
__device__ __forceinline__ u32 pack_pair(float x, float y, u32& lo2) {
    __nv_bfloat162 h2 = __floats2bfloat162_rn(x, y);
    float2 hf = __bfloat1622float2(h2);
    __nv_bfloat162 l2 = __floats2bfloat162_rn(x - hf.x, y - hf.y);
    lo2 = *reinterpret_cast<u32*>(&l2);
    return *reinterpret_cast<u32*>(&h2);
}

// ============================================================================
// Projection: C = X @ W^T + b -> bf16 hi/lo, head-permuted [H*B, S, Dh].
// CTA 128x128, BK=32, 8 warps (4m x 2n), warp tile 32x64. bf16x3 MMA.
// ============================================================================
#define PJ_STR 40   // smem row stride (bf16 elems) for 32-wide k tiles

__global__ __launch_bounds__(256) void proj_kernel(
    const float* __restrict__ X, const float* __restrict__ W,
    const float* __restrict__ bias, int which)
{
    u16* outh = (which == 0) ? g_qh : (which == 1) ? g_kh : g_vh;
    u16* outl = (which == 0) ? g_ql : (which == 1) ? g_kl : g_vl;

    __shared__ u16 sAh[128 * PJ_STR], sAl[128 * PJ_STR];
    __shared__ u16 sBh[128 * PJ_STR], sBl[128 * PJ_STR];

    const int tid = threadIdx.x;
    const int lane = tid & 31;
    const int wid = tid >> 5;
    const int wm = wid >> 1, wn = wid & 1;
    const int m0c = blockIdx.y * 128;
    const int n0c = blockIdx.x * 128;

    const u32 aAh = smem_u32(sAh), aAl = smem_u32(sAl);
    const u32 aBh = smem_u32(sBh), aBl = smem_u32(sBl);

    float acc[2][8][4];
#pragma unroll
    for (int mf = 0; mf < 2; mf++)
#pragma unroll
        for (int nf = 0; nf < 8; nf++)
#pragma unroll
            for (int q = 0; q < 4; q++) acc[mf][nf][q] = 0.0f;

    for (int k0 = 0; k0 < D_MODEL; k0 += 32) {
#pragma unroll
        for (int i = 0; i < 4; i++) {
            int id  = tid + i * 256;        // 1024 float4 slots
            int row = id >> 3;
            int c4  = (id & 7) << 2;        // 0..28
            float4 v = *reinterpret_cast<const float4*>(
                &X[(size_t)(m0c + row) * D_MODEL + k0 + c4]);
            u32 la, ha = (la = 0, pack_pair(v.x, v.y, la));
            u32 lb, hb = (lb = 0, pack_pair(v.z, v.w, lb));
            *reinterpret_cast<u32*>(&sAh[row * PJ_STR + c4])     = ha;
            *reinterpret_cast<u32*>(&sAh[row * PJ_STR + c4 + 2]) = hb;
            *reinterpret_cast<u32*>(&sAl[row * PJ_STR + c4])     = la;
            *reinterpret_cast<u32*>(&sAl[row * PJ_STR + c4 + 2]) = lb;
            float4 w = *reinterpret_cast<const float4*>(
                &W[(size_t)(n0c + row) * D_MODEL + k0 + c4]);
            u32 lc, hc = (lc = 0, pack_pair(w.x, w.y, lc));
            u32 ld, hd = (ld = 0, pack_pair(w.z, w.w, ld));
            *reinterpret_cast<u32*>(&sBh[row * PJ_STR + c4])     = hc;
            *reinterpret_cast<u32*>(&sBh[row * PJ_STR + c4 + 2]) = hd;
            *reinterpret_cast<u32*>(&sBl[row * PJ_STR + c4])     = lc;
            *reinterpret_cast<u32*>(&sBl[row * PJ_STR + c4 + 2]) = ld;
        }
        __syncthreads();

#pragma unroll
        for (int ks = 0; ks < 32; ks += 16) {
            u32 ah[2][4], al[2][4];
#pragma unroll
            for (int mf = 0; mf < 2; mf++) {
                u32 off = ((wm * 32 + mf * 16 + (lane & 15)) * PJ_STR +
                           ks + ((lane >> 4) << 3)) * 2;
                ldm_x4(ah[mf], aAh + off);
                ldm_x4(al[mf], aAl + off);
            }
#pragma unroll
            for (int nf = 0; nf < 8; nf++) {
                int l16 = lane & 15;
                u32 off = ((wn * 64 + nf * 8 + (l16 & 7)) * PJ_STR +
                           ks + ((l16 >> 3) << 3)) * 2;
                u32 bh[2], bl[2];
                ldm_x2(bh, aBh + off);
                ldm_x2(bl, aBl + off);
#pragma unroll
                for (int mf = 0; mf < 2; mf++) {
                    mma16816(acc[mf][nf], ah[mf], bh);
                    mma16816(acc[mf][nf], ah[mf], bl);
                    mma16816(acc[mf][nf], al[mf], bh);
                }
            }
        }
        __syncthreads();
    }

    // epilogue: bias + split + permuted store
#pragma unroll
    for (int mf = 0; mf < 2; mf++) {
#pragma unroll
        for (int nf = 0; nf < 8; nf++) {
            int col = n0c + wn * 64 + nf * 8 + ((lane & 3) << 1);
            float b0 = bias[col], b1 = bias[col + 1];
            int h = col >> 6, d = col & 63;
#pragma unroll
            for (int half = 0; half < 2; half++) {
                int gi = m0c + wm * 32 + mf * 16 + (lane >> 2) + half * 8;
                int b_ = gi >> 11, s_ = gi & (SEQ - 1);
                float x = acc[mf][nf][half * 2]     + b0;
                float y = acc[mf][nf][half * 2 + 1] + b1;
                u32 lo2, hi2 = pack_pair(x, y, lo2);
                size_t idx = ((size_t)(h * BATCH + b_) * SEQ + s_) * DHEAD + d;
                *reinterpret_cast<u32*>(&outh[idx]) = hi2;
                *reinterpret_cast<u32*>(&outl[idx]) = lo2;
            }
        }
    }
}

// ============================================================================
// Attention: CTA = (n, 128 q-rows). Phase 1: stats only (no S writes).
// Phase 2: recompute S, normalize -> attn gmem + P smem -> PV MMA.
// ============================================================================
// smem byte offsets
#define O_QH 0
#define O_QL 18432
#define O_KH 36864
#define O_KL 55296
#define O_VH 73728
#define O_VL 92160
#define O_PH 110592
#define O_PL 145408
#define O_MR 180224
#define O_LR 180736
#define O_PM 181248
#define O_PL2 182272
#define ATTN_SMEM 183296

__device__ __forceinline__ void load_tile64(u16* dst, const u16* src, int tid) {
#pragma unroll
    for (int i = 0; i < 4; i++) {
        int id = tid + i * 256;
        int row = id >> 3, c = id & 7;
        *reinterpret_cast<uint4*>(dst + row * 72 + c * 8) =
            *reinterpret_cast<const uint4*>(src + (size_t)row * 64 + c * 8);
    }
}

__device__ __forceinline__ void qk_mma(u32 aQH, u32 aQL, u32 aKH, u32 aKL,
                                       int m0w, int n0w, int lane,
                                       float sacc[2][8][4]) {
#pragma unroll
    for (int ks = 0; ks < 64; ks += 16) {
        u32 ah[2][4], al[2][4];
#pragma unroll
        for (int mf = 0; mf < 2; mf++) {
            u32 off = ((m0w + mf * 16 + (lane & 15)) * 72 +
                       ks + ((lane >> 4) << 3)) * 2;
            ldm_x4(ah[mf], aQH + off);
            ldm_x4(al[mf], aQL + off);
        }
#pragma unroll
        for (int nf = 0; nf < 8; nf++) {
            int l16 = lane & 15;
            u32 off = ((n0w + nf * 8 + (l16 & 7)) * 72 +
                       ks + ((l16 >> 3) << 3)) * 2;
            u32 bh[2], bl[2];
            ldm_x2(bh, aKH + off);
            ldm_x2(bl, aKL + off);
#pragma unroll
            for (int mf = 0; mf < 2; mf++) {
                mma16816(sacc[mf][nf], ah[mf], bh);
                mma16816(sacc[mf][nf], ah[mf], bl);
                mma16816(sacc[mf][nf], al[mf], bh);
            }
        }
    }
}

__global__ __launch_bounds__(256) void attn_kernel(
    float* __restrict__ attn_out, float* __restrict__ ctx_out)
{
    extern __shared__ char sm[];
    u16* sQH = (u16*)(sm + O_QH);  u16* sQL = (u16*)(sm + O_QL);
    u16* sKH = (u16*)(sm + O_KH);  u16* sKL = (u16*)(sm + O_KL);
    u16* sVH = (u16*)(sm + O_VH);  u16* sVL = (u16*)(sm + O_VL);
    u16* sPH = (u16*)(sm + O_PH);  u16* sPL = (u16*)(sm + O_PL);
    float* mrow = (float*)(sm + O_MR);
    float* lrow = (float*)(sm + O_LR);
    float* pm   = (float*)(sm + O_PM);
    float* pl   = (float*)(sm + O_PL2);

    const u32 aQH = smem_u32(sQH), aQL = smem_u32(sQL);
    const u32 aKH = smem_u32(sKH), aKL = smem_u32(sKL);
    const u32 aVH = smem_u32(sVH), aVL = smem_u32(sVL);
    const u32 aPH = smem_u32(sPH), aPL = smem_u32(sPL);

    const int tid = threadIdx.x;
    const int lane = tid & 31;
    const int wid = tid >> 5;
    const int wm = wid >> 1, wn = wid & 1;
    const int m0w = wm * 32, n0w = wn * 64;
    const int n  = blockIdx.y;
    const int r0 = blockIdx.x * 128;
    const float scale = 0.125f;

    const size_t nbase = (size_t)n * SEQ * DHEAD;
    float* An = attn_out + (size_t)n * SEQ * SEQ;

    load_tile64(sQH, g_qh + nbase + (size_t)r0 * DHEAD, tid);
    load_tile64(sQL, g_ql + nbase + (size_t)r0 * DHEAD, tid);
    if (tid < 128) { mrow[tid] = -1e30f; lrow[tid] = 0.0f; }

    // ---------------- Phase 1: stats ----------------
    for (int kt = 0; kt < SEQ / 128; kt++) {
        load_tile64(sKH, g_kh + nbase + (size_t)kt * 128 * DHEAD, tid);
        load_tile64(sKL, g_kl + nbase + (size_t)kt * 128 * DHEAD, tid);
        __syncthreads();

        float sacc[2][8][4];
#pragma unroll
        for (int mf = 0; mf < 2; mf++)
#pragma unroll
            for (int nf = 0; nf < 8; nf++)
#pragma unroll
                for (int q = 0; q < 4; q++) sacc[mf][nf][q] = 0.0f;
        qk_mma(aQH, aQL, aKH, aKL, m0w, n0w, lane, sacc);

#pragma unroll
        for (int mf = 0; mf < 2; mf++) {
#pragma unroll
            for (int half = 0; half < 2; half++) {
                int rl = m0w + mf * 16 + (lane >> 2) + half * 8;
                float mx = -1e30f;
#pragma unroll
                for (int nf = 0; nf < 8; nf++) {
                    mx = fmaxf(mx, fmaxf(sacc[mf][nf][half * 2] * scale,
                                         sacc[mf][nf][half * 2 + 1] * scale));
                }
                mx = fmaxf(mx, __shfl_xor_sync(0xffffffffu, mx, 1));
                mx = fmaxf(mx, __shfl_xor_sync(0xffffffffu, mx, 2));
                float sum = 0.0f;
#pragma unroll
                for (int nf = 0; nf < 8; nf++) {
                    sum += __expf(sacc[mf][nf][half * 2] * scale - mx);
                    sum += __expf(sacc[mf][nf][half * 2 + 1] * scale - mx);
                }
                sum += __shfl_xor_sync(0xffffffffu, sum, 1);
                sum += __shfl_xor_sync(0xffffffffu, sum, 2);
                if ((lane & 3) == 0) { pm[rl * 2 + wn] = mx; pl[rl * 2 + wn] = sum; }
            }
        }
        __syncthreads();
        if (tid < 128) {
            float m0 = pm[tid * 2], m1 = pm[tid * 2 + 1];
            float mt = fmaxf(m0, m1);
            float lt = pl[tid * 2] * __expf(m0 - mt) + pl[tid * 2 + 1] * __expf(m1 - mt);
            float mo = mrow[tid];
            float mn = fmaxf(mo, mt);
            lrow[tid] = lrow[tid] * __expf(mo - mn) + lt * __expf(mt - mn);
            mrow[tid] = mn;
        }
        __syncthreads();
    }

    if (tid < 128) lrow[tid] = 1.0f / lrow[tid];

    // ---------------- Phase 2: recompute + normalize + PV ----------------
    float cacc[2][4][4];
#pragma unroll
    for (int mf = 0; mf < 2; mf++)
#pragma unroll
        for (int nf = 0; nf < 4; nf++)
#pragma unroll
            for (int q = 0; q < 4; q++) cacc[mf][nf][q] = 0.0f;

    for (int kt = 0; kt < SEQ / 128; kt++) {
        load_tile64(sKH, g_kh + nbase + (size_t)kt * 128 * DHEAD, tid);
        load_tile64(sKL, g_kl + nbase + (size_t)kt * 128 * DHEAD, tid);
        load_tile64(sVH, g_vh + nbase + (size_t)kt * 128 * DHEAD, tid);
        load_tile64(sVL, g_vl + nbase + (size_t)kt * 128 * DHEAD, tid);
        __syncthreads();

        float sacc[2][8][4];
#pragma unroll
        for (int mf = 0; mf < 2; mf++)
#pragma unroll
            for (int nf = 0; nf < 8; nf++)
#pragma unroll
                for (int q = 0; q < 4; q++) sacc[mf][nf][q] = 0.0f;
        qk_mma(aQH, aQL, aKH, aKL, m0w, n0w, lane, sacc);

#pragma unroll
        for (int mf = 0; mf < 2; mf++) {
#pragma unroll
            for (int half = 0; half < 2; half++) {
                int rl = m0w + mf * 16 + (lane >> 2) + half * 8;
                float mr = mrow[rl], li = lrow[rl];
                float* anrow = An + (size_t)(r0 + rl) * SEQ + kt * 128;
#pragma unroll
                for (int nf = 0; nf < 8; nf++) {
                    float p0 = __expf(sacc[mf][nf][half * 2] * scale - mr) * li;
                    float p1 = __expf(sacc[mf][nf][half * 2 + 1] * scale - mr) * li;
                    int col = n0w + nf * 8 + ((lane & 3) << 1);
                    *reinterpret_cast<float2*>(anrow + col) = make_float2(p0, p1);
                    u32 lo2, hi2 = pack_pair(p0, p1, lo2);
                    *reinterpret_cast<u32*>(&sPH[rl * 136 + col]) = hi2;
                    *reinterpret_cast<u32*>(&sPL[rl * 136 + col]) = lo2;
                }
            }
        }
        __syncthreads();

        // PV: ctx += P[128x128] @ V[128x64]; warp tile 32x32
#pragma unroll
        for (int ks = 0; ks < 8; ks++) {
            int k0 = ks * 16;
            u32 ah[2][4], al[2][4];
#pragma unroll
            for (int mf = 0; mf < 2; mf++) {
                u32 off = ((m0w + mf * 16 + (lane & 15)) * 136 +
                           k0 + ((lane >> 4) << 3)) * 2;
                ldm_x4(ah[mf], aPH + off);
                ldm_x4(al[mf], aPL + off);
            }
#pragma unroll
            for (int nf = 0; nf < 4; nf++) {
                int d0 = wn * 32 + nf * 8;
                u32 off = ((k0 + (lane & 15)) * 72 + d0) * 2;
                u32 bh[2], bl[2];
                ldm_x2t(bh, aVH + off);
                ldm_x2t(bl, aVL + off);
#pragma unroll
                for (int mf = 0; mf < 2; mf++) {
                    mma16816(cacc[mf][nf], ah[mf], bh);
                    mma16816(cacc[mf][nf], ah[mf], bl);
                    mma16816(cacc[mf][nf], al[mf], bh);
                }
            }
        }
        __syncthreads();
    }

    // ctx epilogue: out[b][s][h*64+d]
    const int h = n >> 1, b_ = n & 1;
#pragma unroll
    for (int mf = 0; mf < 2; mf++) {
#pragma unroll
        for (int nf = 0; nf < 4; nf++) {
            int d = wn * 32 + nf * 8 + ((lane & 3) << 1);
#pragma unroll
            for (int half = 0; half < 2; half++) {
                int s_ = r0 + m0w + mf * 16 + (lane >> 2) + half * 8;
                float2 v = make_float2(cacc[mf][nf][half * 2],
                                       cacc[mf][nf][half * 2 + 1]);
                *reinterpret_cast<float2*>(
                    &ctx_out[((size_t)b_ * SEQ + s_) * D_MODEL + h * 64 + d]) = v;
            }
        }
    }
}

// ============================================================================
extern "C" void kernel_launch(void* const* d_in, const int* in_sizes, int n_in,
                              void* d_out, int out_size)
{
    const float* query = (const float*)d_in[0];
    const float* key_  = (const float*)d_in[1];
    const float* value = (const float*)d_in[2];
    const float* Wq = (const float*)d_in[3];
    const float* bq = (const float*)d_in[4];
    const float* Wk = (const float*)d_in[5];
    const float* bk = (const float*)d_in[6];
    const float* Wv = (const float*)d_in[7];
    const float* bv = (const float*)d_in[8];

    cudaFuncSetAttribute(attn_kernel, cudaFuncAttributeMaxDynamicSharedMemorySize,
                         ATTN_SMEM);

    const long long CTX_N  = (long long)MROWS * D_MODEL;   // 4194304
    const long long ATTN_N = (long long)HB * SEQ * SEQ;    // 134217728
    float* ctx_out;
    float* attn_out;
    void* sym;
    if ((long long)out_size >= CTX_N + ATTN_N) {
        ctx_out  = (float*)d_out;
        attn_out = (float*)d_out + CTX_N;
    } else if ((long long)out_size == ATTN_N) {
        attn_out = (float*)d_out;
        cudaGetSymbolAddress(&sym, g_ctx_fb);
        ctx_out = (float*)sym;
    } else {
        ctx_out = (float*)d_out;
        cudaGetSymbolAddress(&sym, g_attn_fb);
        attn_out = (float*)sym;
    }

    dim3 pgrid(D_MODEL / 128, MROWS / 128);   // (8, 32)
    proj_kernel<<<pgrid, 256>>>(query, Wq, bq, 0);
    proj_kernel<<<pgrid, 256>>>(key_,  Wk, bk, 1);
    proj_kernel<<<pgrid, 256>>>(value, Wv, bv, 2);

    dim3 agrid(SEQ / 128, HB);                // (16, 32)
    attn_kernel<<<agrid, 256, ATTN_SMEM>>>(attn_out, ctx_out);
}